// round 12
// baseline (speedup 1.0000x reference)
#include <cuda_runtime.h>
#include <math.h>

#define BATCH  1024
#define DIM    256
#define TSTEPS 128
#define HID    256
#define NOUT   64
#define JC     80     // j-rows of each hidden matrix cached in smem

__device__ float g_cur1[(size_t)TSTEPS * BATCH * HID];  // [t][b][h]
__device__ float g_WTin[DIM * HID];        // [d][h]
__device__ float g_WTh [HID * HID];        // [j][h]
__device__ float g_WTh1[HID * HID];        // [j][h]
__device__ float g_Wfa [HID * NOUT * 2];   // [j][o][2] (wf, wa)

typedef unsigned long long ull;
typedef unsigned int uint32;

__device__ __forceinline__ void ffma2(ull& acc, ull a, ull b) {
    asm("fma.rn.f32x2 %0, %1, %2, %0;" : "+l"(acc) : "l"(a), "l"(b));
}
__device__ __forceinline__ ull mul2(ull a, ull b) {
    ull r; asm("mul.rn.f32x2 %0, %1, %2;" : "=l"(r) : "l"(a), "l"(b)); return r;
}
__device__ __forceinline__ ull add2(ull a, ull b) {
    ull r; asm("add.rn.f32x2 %0, %1, %2;" : "=l"(r) : "l"(a), "l"(b)); return r;
}
__device__ __forceinline__ ull pack2(float x, float y) {
    ull r; asm("mov.b64 %0, {%1, %2};" : "=l"(r) : "f"(x), "f"(y)); return r;
}
__device__ __forceinline__ ull pack2u(uint32 x, uint32 y) {
    ull r; asm("mov.b64 %0, {%1, %2};" : "=l"(r) : "r"(x), "r"(y)); return r;
}
__device__ __forceinline__ void unpack2(ull v, float& x, float& y) {
    asm("mov.b64 {%0, %1}, %2;" : "=f"(x), "=f"(y) : "l"(v));
}
__device__ __forceinline__ float clamp01(float v) {
    return fminf(fmaxf(v, 0.0f), 1.0f);
}
// bf16 spike constants: 1.0f -> 0x3F80 (exact), 0.0f -> 0x0000.
#define SPIKE1 0x3F80u

__global__ void dummy_k() {}

// ---------------------------------------------------------------------------
__global__ void prep_weights(const float* __restrict__ W_in,
                             const float* __restrict__ W_h,
                             const float* __restrict__ W_h1,
                             const float* __restrict__ W_f,
                             const float* __restrict__ W_a) {
    if (blockIdx.z == 3) {
        int idx = (blockIdx.y * 8 + blockIdx.x) * 256 + threadIdx.y * 32 + threadIdx.x;
        int j = idx >> 6, oo = idx & 63;
        g_Wfa[idx * 2]     = W_f[oo * HID + j];
        g_Wfa[idx * 2 + 1] = W_a[oo * HID + j];
        return;
    }
    __shared__ float tile[32][33];
    const float* in; float* out;
    switch (blockIdx.z) {
        case 0:  in = W_in; out = g_WTin; break;
        case 1:  in = W_h;  out = g_WTh;  break;
        default: in = W_h1; out = g_WTh1; break;
    }
    int c0 = blockIdx.x * 32, r0 = blockIdx.y * 32;
    int tx = threadIdx.x, ty = threadIdx.y;
    #pragma unroll
    for (int k = 0; k < 32; k += 8)
        tile[ty + k][tx] = in[(r0 + ty + k) * 256 + (c0 + tx)];
    __syncthreads();
    #pragma unroll
    for (int k = 0; k < 32; k += 8)
        out[(c0 + ty + k) * 256 + (r0 + tx)] = tile[tx][ty + k];
}

// ---------------------------------------------------------------------------
// cur1[t][b][h] = sum_d x[b][d][t]*W_in[h][d].  (unchanged — bit-exact)
// ---------------------------------------------------------------------------
__global__ void __launch_bounds__(512) precompute_cur1(const float* __restrict__ x) {
    extern __shared__ __align__(16) float xS[];
    ull* xsu = reinterpret_cast<ull*>(xS);
    const int tid = threadIdx.x;
    const int t0  = blockIdx.x * 64;
    const int b   = blockIdx.y;

    {
        int d = tid >> 1, th = (tid & 1) * 32;
        const float4* xp = reinterpret_cast<const float4*>(
            x + ((size_t)b * DIM + d) * TSTEPS + t0 + th);
        #pragma unroll
        for (int q = 0; q < 8; ++q) {
            float4 v = __ldg(xp + q);
            xsu[d * 32 + th / 2 + 2 * q]     = pack2(v.x, v.y);
            xsu[d * 32 + th / 2 + 2 * q + 1] = pack2(v.z, v.w);
        }
    }
    __syncthreads();

    const int hp = tid & 127;
    const int tg = tid >> 7;
    ull acc[16];
    #pragma unroll
    for (int i = 0; i < 16; ++i) acc[i] = 0ull;

    const ull* gw = reinterpret_cast<const ull*>(g_WTin) + hp;
    #pragma unroll 1
    for (int blk = 0; blk < 32; ++blk) {
        ull wv[8];
        #pragma unroll
        for (int i = 0; i < 8; ++i)
            wv[i] = __ldg(gw + (blk * 8 + i) * 128);
        #pragma unroll
        for (int i = 0; i < 8; ++i) {
            const int j = blk * 8 + i;
            float w0, w1; unpack2(wv[i], w0, w1);
            ull wa = pack2(w0, w0), wb = pack2(w1, w1);
            const ull* xr = xsu + j * 32 + tg * 8;
            #pragma unroll
            for (int tp = 0; tp < 8; ++tp) {
                ull xv = xr[tp];
                ffma2(acc[tp],     xv, wa);
                ffma2(acc[8 + tp], xv, wb);
            }
        }
    }
    #pragma unroll
    for (int tp = 0; tp < 8; ++tp) {
        float a0, a1, b0, b1;
        unpack2(acc[tp], a0, a1);
        unpack2(acc[8 + tp], b0, b1);
        int t = t0 + tg * 16 + 2 * tp;
        *reinterpret_cast<ull*>(g_cur1 + ((size_t)t * BATCH + b) * HID + 2 * hp)
            = pack2(a0, b0);
        *reinterpret_cast<ull*>(g_cur1 + ((size_t)(t + 1) * BATCH + b) * HID + 2 * hp)
            = pack2(a1, b1);
    }
}

// ---------------------------------------------------------------------------
// bf16 spike unpack: row r f32 bits = (u16 bf16) << 16. Exact for 0.0/1.0.
// sv = [r1b:r0b] -> s01 = f32x2 (r0, r1)
// ---------------------------------------------------------------------------
__device__ __forceinline__ void spk2(uint32 p, ull& s01) {
    s01 = pack2u(p << 16, p & 0xFFFF0000u);
}

// ---------------------------------------------------------------------------
// Uncached-j helpers: blocks of 16, register double-buffered.
// Spike buffers are bf16: [j][8 rows] = 16B per j; this thread reads 8B (4 rows).
// ---------------------------------------------------------------------------
__device__ __forceinline__ void ldblk16(ull* buf, const ull* gb, int blk) {
    #pragma unroll
    for (int i = 0; i < 16; ++i)
        buf[i] = __ldg(gb + (JC + blk * 16 + i) * 128);
}
__device__ __forceinline__ void useblk16(const ull* buf, const char* sInb,
                                         int blk, ull* acc) {
    #pragma unroll
    for (int i = 0; i < 16; ++i) {
        float w0, w1; unpack2(buf[i], w0, w1);
        ull wa = pack2(w0, w0), wb = pack2(w1, w1);
        uint2 sv = *reinterpret_cast<const uint2*>(sInb + (JC + blk * 16 + i) * 16);
        ull s01, s23;
        spk2(sv.x, s01);
        spk2(sv.y, s23);
        ffma2(acc[0], s01, wa); ffma2(acc[1], s23, wa);
        ffma2(acc[2], s01, wb); ffma2(acc[3], s23, wb);
    }
}

// ---------------------------------------------------------------------------
// Hidden layer: thread owns 2 h x 4 rows. Chains serial over j — bit-exact.
// ---------------------------------------------------------------------------
__device__ __forceinline__ void layerX(
    const float* sW, const ull* __restrict__ gWp, const char* sIn,
    int rg, int hp,
    float bias0, float bias1, float bc0, float bc1, float thr0, float thr1,
    float* m /*[hh*4+r]*/, char* sOut)
{
    ull acc[4] = {0ull, 0ull, 0ull, 0ull};
    const char* sInb = sIn + rg * 8;
    const ull* sWp = reinterpret_cast<const ull*>(sW) + hp;
    #pragma unroll 8
    for (int j = 0; j < JC; ++j) {
        float w0, w1; unpack2(sWp[j * 128], w0, w1);
        ull wa = pack2(w0, w0), wb = pack2(w1, w1);
        uint2 sv = *reinterpret_cast<const uint2*>(sInb + j * 16);
        ull s01, s23;
        spk2(sv.x, s01);
        spk2(sv.y, s23);
        ffma2(acc[0], s01, wa); ffma2(acc[1], s23, wa);
        ffma2(acc[2], s01, wb); ffma2(acc[3], s23, wb);
    }
    // 176 uncached rows = 11 blocks of 16, double-buffered
    const ull* gb = gWp + hp;
    ull bufA[16], bufB[16];
    ldblk16(bufA, gb, 0);
    #pragma unroll
    for (int b2 = 0; b2 < 5; ++b2) {
        ldblk16(bufB, gb, 2 * b2 + 1);
        useblk16(bufA, sInb, 2 * b2, acc);
        ldblk16(bufA, gb, 2 * b2 + 2);
        useblk16(bufB, sInb, 2 * b2 + 1, acc);
    }
    useblk16(bufA, sInb, 10, acc);

    #pragma unroll
    for (int hh = 0; hh < 2; ++hh) {
        float bias = hh ? bias1 : bias0;
        float bc   = hh ? bc1 : bc0;
        float thr  = hh ? thr1 : thr0;
        uint32 w01 = 0, w23 = 0;
        #pragma unroll
        for (int p = 0; p < 2; ++p) {
            float c0, c1; unpack2(acc[hh * 2 + p], c0, c1);
            float* mm = m + hh * 4 + 2 * p;
            float ca = __fadd_rn(c0, bias);
            float cb = __fadd_rn(c1, bias);
            float ra = (mm[0] > thr) ? thr : 0.0f;     // reset from PREV mem
            float rb = (mm[1] > thr) ? thr : 0.0f;
            float na = __fsub_rn(__fadd_rn(__fmul_rn(bc, mm[0]), ca), ra);
            float nb = __fsub_rn(__fadd_rn(__fmul_rn(bc, mm[1]), cb), rb);
            mm[0] = na; mm[1] = nb;
            uint32 sa = (na > thr) ? SPIKE1 : 0u;
            uint32 sb = (nb > thr) ? SPIKE1 : 0u;
            if (p == 0) w01 = sa | (sb << 16);
            else        w23 = sa | (sb << 16);
        }
        *reinterpret_cast<ull*>(sOut + (2 * hp + hh) * 16 + rg * 8) =
            pack2u(w01, w23);
    }
}

// ---------------------------------------------------------------------------
// Recurrent kernel: 128 CTAs x 512 threads.
//  A (warps 0-7): hp = warp*16 + (lane>>1), rg = lane&1. 2 h x 4 rows.
//    Spikes stored as bf16 [j][8 rows]: 1-phase LDS.64 reads.
//  B (warps 8-15): output-LI GEMM for step k-1; Wfa from global (L2-hot)
// smem: sWh 80KB | sWh1 80KB | spike bufs 4x4KB | scr 16KB = 192KB
// ---------------------------------------------------------------------------
#define SMEM_BYTES (2 * JC * HID * 4 + 4 * 4096 + 16384)

__global__ void __launch_bounds__(512, 1) snn_rec(
    const float* __restrict__ b_in,  const float* __restrict__ beta1,
    const float* __restrict__ thr1,
    const float* __restrict__ b_h,   const float* __restrict__ beta2,
    const float* __restrict__ thr2,
    const float* __restrict__ b_h1,
    const float* __restrict__ b_f,   const float* __restrict__ beta_f,
    const float* __restrict__ b_a,   const float* __restrict__ beta_a,
    float* __restrict__ out)
{
    extern __shared__ __align__(16) char dsmc[];
    float* sWh  = reinterpret_cast<float*>(dsmc);
    float* sWh1 = sWh + JC * HID;
    char*  s1P  = reinterpret_cast<char*>(sWh1 + JC * HID);   // 4096B each
    char*  s2P  = s1P + 4096;
    char*  s3a  = s2P + 4096;
    char*  s3b  = s3a + 4096;
    ull*   scr  = reinterpret_cast<ull*>(s3b + 4096);         // 16KB

    const int tid = threadIdx.x;
    const int b0  = blockIdx.x * 8;

    for (int i = tid; i < JC * HID; i += 512) {
        sWh[i]  = g_WTh[i];
        sWh1[i] = g_WTh1[i];
    }

    if (tid < 256) {
        // ===================== A role =====================
        const int w    = tid >> 5;
        const int lane = tid & 31;
        const int hp   = w * 16 + (lane >> 1);   // 0..127
        const int rg   = lane & 1;               // row-half
        const int h0 = 2 * hp, h1 = h0 + 1;
        const float bin0 = b_in[h0],  bin1 = b_in[h1];
        const float b1c0 = clamp01(beta1[h0]), b1c1 = clamp01(beta1[h1]);
        const float t10 = thr1[h0],  t11 = thr1[h1];
        const float bh0 = b_h[h0],   bh1 = b_h[h1];
        const float b2c0 = clamp01(beta2[h0]), b2c1 = clamp01(beta2[h1]);
        const float t20 = thr2[h0],  t21 = thr2[h1];
        const float bh10 = b_h1[h0], bh11 = b_h1[h1];

        float m1[8], m2[8], m3[8];
        #pragma unroll
        for (int i = 0; i < 8; ++i) { m1[i] = 0.f; m2[i] = 0.f; m3[i] = 0.f; }

        const int rowbase = b0 + rg * 4;
        ull c1p[4];
        #pragma unroll
        for (int r = 0; r < 4; ++r)
            c1p[r] = __ldg(reinterpret_cast<const ull*>(
                g_cur1 + ((size_t)0 * BATCH + rowbase + r) * HID + h0));

        __syncthreads();   // weight caches ready

        const ull* gWh  = reinterpret_cast<const ull*>(g_WTh);
        const ull* gWh1 = reinterpret_cast<const ull*>(g_WTh1);

        for (int k = 0; k <= TSTEPS; ++k) {
            if (k < TSTEPS) {
                // ---- LIF layer 1: 2h x 4 rows -> bf16 spikes ----
                uint32 a01 = 0, a23 = 0, b01 = 0, b23 = 0;
                #pragma unroll
                for (int p = 0; p < 2; ++p) {
                    float ca0, cb0, ca1, cb1;
                    unpack2(c1p[2 * p],     ca0, ca1);   // row 2p:   (h0, h1)
                    unpack2(c1p[2 * p + 1], cb0, cb1);   // row 2p+1: (h0, h1)
                    float x0 = __fadd_rn(ca0, bin0);
                    float x1 = __fadd_rn(cb0, bin0);
                    float r0 = (m1[2 * p] > t10) ? t10 : 0.0f;
                    float r1 = (m1[2 * p + 1] > t10) ? t10 : 0.0f;
                    float n0 = __fsub_rn(__fadd_rn(__fmul_rn(b1c0, m1[2 * p]), x0), r0);
                    float n1 = __fsub_rn(__fadd_rn(__fmul_rn(b1c0, m1[2 * p + 1]), x1), r1);
                    m1[2 * p] = n0; m1[2 * p + 1] = n1;
                    uint32 sa = (n0 > t10) ? SPIKE1 : 0u;
                    uint32 sb = (n1 > t10) ? SPIKE1 : 0u;
                    if (p == 0) a01 = sa | (sb << 16); else a23 = sa | (sb << 16);
                    float y0 = __fadd_rn(ca1, bin1);
                    float y1 = __fadd_rn(cb1, bin1);
                    float s0 = (m1[4 + 2 * p] > t11) ? t11 : 0.0f;
                    float s1 = (m1[4 + 2 * p + 1] > t11) ? t11 : 0.0f;
                    float q0 = __fsub_rn(__fadd_rn(__fmul_rn(b1c1, m1[4 + 2 * p]), y0), s0);
                    float q1 = __fsub_rn(__fadd_rn(__fmul_rn(b1c1, m1[4 + 2 * p + 1]), y1), s1);
                    m1[4 + 2 * p] = q0; m1[4 + 2 * p + 1] = q1;
                    uint32 ta = (q0 > t11) ? SPIKE1 : 0u;
                    uint32 tb = (q1 > t11) ? SPIKE1 : 0u;
                    if (p == 0) b01 = ta | (tb << 16); else b23 = ta | (tb << 16);
                }
                *reinterpret_cast<ull*>(s1P + h0 * 16 + rg * 8) = pack2u(a01, a23);
                *reinterpret_cast<ull*>(s1P + h1 * 16 + rg * 8) = pack2u(b01, b23);

                if (k + 1 < TSTEPS) {
                    #pragma unroll
                    for (int r = 0; r < 4; ++r)
                        c1p[r] = __ldg(reinterpret_cast<const ull*>(
                            g_cur1 + ((size_t)(k + 1) * BATCH + rowbase + r) * HID + h0));
                }
                asm volatile("bar.sync 1, 256;" ::: "memory");

                layerX(sWh, gWh, s1P, rg, hp,
                       bh0, bh1, b2c0, b2c1, t20, t21, m2, s2P);
                asm volatile("bar.sync 1, 256;" ::: "memory");

                char* s3 = (k & 1) ? s3b : s3a;
                layerX(sWh1, gWh1, s2P, rg, hp,
                       bh10, bh11, b2c0, b2c1, t20, t21, m3, s3);  // bug preserved
            }
            __syncthreads();   // publish s3(k) to B
        }
    } else {
        // ===================== B role =====================
        const int bt = tid - 256;
        const int o  = bt & 63;
        const int q  = bt >> 6;
        const ull bias_fa = pack2(b_f[o], b_a[o]);
        const ull beta_fa = pack2(clamp01(beta_f[o]), clamp01(beta_a[o]));
        ull macc0 = pack2(0.f, 0.f), macc1 = macc0;
        const ull* wrow = reinterpret_cast<const ull*>(g_Wfa);

        __syncthreads();

        for (int k = 0; k <= TSTEPS; ++k) {
            if (k >= 1) {
                const char* s3 = ((k - 1) & 1) ? s3b : s3a;
                ull accF[4] = {0ull, 0ull, 0ull, 0ull};
                ull accA[4] = {0ull, 0ull, 0ull, 0ull};
                const int j0 = q * 64;
                #pragma unroll 8
                for (int jj = 0; jj < 64; ++jj) {
                    int j = j0 + jj;
                    ull wv = __ldg(wrow + j * 64 + o);
                    float wf, wa; unpack2(wv, wf, wa);
                    ull wf2 = pack2(wf, wf), wa2 = pack2(wa, wa);
                    uint4 sv = *reinterpret_cast<const uint4*>(s3 + j * 16);
                    ull s01, s23, s45, s67;
                    spk2(sv.x, s01);
                    spk2(sv.y, s23);
                    spk2(sv.z, s45);
                    spk2(sv.w, s67);
                    ffma2(accF[0], s01, wf2); ffma2(accF[1], s23, wf2);
                    ffma2(accF[2], s45, wf2); ffma2(accF[3], s67, wf2);
                    ffma2(accA[0], s01, wa2); ffma2(accA[1], s23, wa2);
                    ffma2(accA[2], s45, wa2); ffma2(accA[3], s67, wa2);
                }
                #pragma unroll
                for (int r2 = 0; r2 < 4; ++r2) {
                    scr[r2 * 256 + q * 64 + o]        = accF[r2];
                    scr[1024 + r2 * 256 + q * 64 + o] = accA[r2];
                }
                asm volatile("bar.sync 2, 256;" ::: "memory");
                ull Fs = pack2(0.f, 0.f), As = Fs;
                #pragma unroll
                for (int qq = 0; qq < 4; ++qq) {
                    Fs = add2(Fs, scr[q * 256 + qq * 64 + o]);
                    As = add2(As, scr[1024 + q * 256 + qq * 64 + o]);
                }
                float f0, f1, a0, a1;
                unpack2(Fs, f0, f1);
                unpack2(As, a0, a1);
                macc0 = add2(mul2(beta_fa, macc0), add2(pack2(f0, a0), bias_fa));
                macc1 = add2(mul2(beta_fa, macc1), add2(pack2(f1, a1), bias_fa));
            }
            __syncthreads();
        }

        float mf0, ma0, mf1, ma1;
        unpack2(macc0, mf0, ma0);
        unpack2(macc1, mf1, ma1);
        int row = b0 + 2 * q;
        out[(size_t)row * NOUT + o]                              = 1.0f / (1.0f + expf(-mf0));
        out[(size_t)(row + 1) * NOUT + o]                        = 1.0f / (1.0f + expf(-mf1));
        out[(size_t)BATCH * NOUT + (size_t)row * NOUT + o]       = 1.0f / (1.0f + expf(-ma0));
        out[(size_t)BATCH * NOUT + (size_t)(row + 1) * NOUT + o] = 1.0f / (1.0f + expf(-ma1));
    }
}

// ---------------------------------------------------------------------------
extern "C" void kernel_launch(void* const* d_in, const int* in_sizes, int n_in,
                              void* d_out, int out_size) {
    const float* x      = (const float*)d_in[0];
    const float* W_in   = (const float*)d_in[1];
    const float* b_in   = (const float*)d_in[2];
    const float* beta1  = (const float*)d_in[3];
    const float* thr1   = (const float*)d_in[4];
    const float* W_h    = (const float*)d_in[5];
    const float* b_h    = (const float*)d_in[6];
    const float* beta2  = (const float*)d_in[7];
    const float* thr2   = (const float*)d_in[8];
    const float* W_h1   = (const float*)d_in[9];
    const float* b_h1   = (const float*)d_in[10];
    const float* W_f    = (const float*)d_in[11];
    const float* b_f    = (const float*)d_in[12];
    const float* beta_f = (const float*)d_in[13];
    const float* W_a    = (const float*)d_in[14];
    const float* b_a    = (const float*)d_in[15];
    const float* beta_a = (const float*)d_in[16];
    float* out = (float*)d_out;

    cudaFuncSetAttribute(snn_rec, cudaFuncAttributeMaxDynamicSharedMemorySize,
                         SMEM_BYTES);
    cudaFuncSetAttribute(precompute_cur1,
                         cudaFuncAttributeMaxDynamicSharedMemorySize, 65536);

    dummy_k<<<1, 1>>>();
    prep_weights<<<dim3(8, 8, 4), dim3(32, 8)>>>(W_in, W_h, W_h1, W_f, W_a);
    precompute_cur1<<<dim3(2, BATCH), 512, 65536>>>(x);
    snn_rec<<<BATCH / 8, 512, SMEM_BYTES>>>(b_in, beta1, thr1, b_h, beta2, thr2,
                                            b_h1, b_f, beta_f, b_a, beta_a, out);
}